// round 13
// baseline (speedup 1.0000x reference)
#include <cuda_runtime.h>
#include <math.h>
#include <stdint.h>

// ---------------- problem constants ----------------
#define NN   2048
#define NT   256                // threads per CTA (two 128-thread CG groups)
#define GT   128                // group size
#define NPT  16                 // elements per thread in x/y CG (NN/GT)
#define NP2  8                  // elements per thread in block-wide ops (NN/NT)
#define BB   8
#define KK   4
#define CL   4                  // cluster size: 4 modes (x+y inside each CTA)
#define NGRID (BB * CL)         // 32 CTAs
#define EN   (NN / CL)          // 512 elements per rank in epilogue gather
#define TWO_PI_F 6.283185307179586f

// output layout (flattened tuple, fp32)
#define OUT_EIF 0
#define OUT_XM  65536
#define OUT_YM  131072
#define OUT_BSX 196608
#define OUT_BSY 212992
#define OUT_LAM 229376
#define OUT_SC  245760

// ---------------- barrier helper ----------------
template<int GSIZE>
__device__ __forceinline__ void barg(int barId)
{
    if (GSIZE == NT) __syncthreads();
    else asm volatile("bar.sync %0, %1;" :: "r"(barId), "r"(GSIZE) : "memory");
}

// group reduce -> 16 partials -> 1 barrier -> every thread sums 4x float4.
//  GSIZE=128: 3 shuffles (8-lane groups); GSIZE=256: 4 shuffles (16-lane).
template<int GSIZE>
__device__ __forceinline__ float gred(float v, float* sred, int gtid, int barId)
{
    if (GSIZE == 128) {
#pragma unroll
        for (int o = 4; o > 0; o >>= 1) v += __shfl_down_sync(0xffffffffu, v, o);
        if ((gtid & 7) == 0) sred[gtid >> 3] = v;
    } else {
#pragma unroll
        for (int o = 8; o > 0; o >>= 1) v += __shfl_down_sync(0xffffffffu, v, o);
        if ((gtid & 15) == 0) sred[gtid >> 4] = v;
    }
    barg<GSIZE>(barId);
    float4 q0 = reinterpret_cast<float4*>(sred)[0];
    float4 q1 = reinterpret_cast<float4*>(sred)[1];
    float4 q2 = reinterpret_cast<float4*>(sred)[2];
    float4 q3 = reinterpret_cast<float4*>(sred)[3];
    float s0 = (q0.x + q0.y) + (q0.z + q0.w);
    float s1 = (q1.x + q1.y) + (q1.z + q1.w);
    float s2 = (q2.x + q2.y) + (q2.z + q2.w);
    float s3 = (q3.x + q3.y) + (q3.z + q3.w);
    return (s0 + s1) + (s2 + s3);
}

// interior 5-point stencil of (D^T D): [1,-4,6,-4,1]; w[k] = elem(base-2+k)
#define STEN5(w, c) ((w)[c] - 4.f*(w)[(c)+1] + 6.f*(w)[(c)+2] - 4.f*(w)[(c)+3] + (w)[(c)+4])

// Boundary rows, exact reference expressions, recomputed on edge threads only.
template<int NPT2>
__device__ __forceinline__ void fix_bounds(float coef, const float* d,
                                           const float* v, float* Av,
                                           bool isF, bool isL)
{
    if (isF) {
        Av[0] = coef * (2.f*v[0] - 3.f*v[1] + v[2]) + d[0]*v[0];
        Av[1] = coef * (-3.f*v[0] + 6.f*v[1] - 4.f*v[2] + v[3]) + d[1]*v[1];
    }
    if (isL) {
        Av[NPT2-2] = coef * (v[NPT2-4] - 4.f*v[NPT2-3] + 6.f*v[NPT2-2] - 3.f*v[NPT2-1])
                   + d[NPT2-2]*v[NPT2-2];
        Av[NPT2-1] = coef * (v[NPT2-3] - 3.f*v[NPT2-2] + 2.f*v[NPT2-1])
                   + d[NPT2-1]*v[NPT2-1];
    }
}

// Group-cooperative CG (R11 numerics): explicit rsnew = ||r-a*Ap||^2,
// freeze == break. p in registers; r halos via SMEM float2; neighbor p halos
// reconstructed as r_halo + beta*p_halo_old. sp = element-0 view with 2 guard
// floats each side (zeroed; never used by boundary math). 2 barriers/iter.
template<int GSIZE, int NPT2>
__device__ __forceinline__ void cg_solve(int gtid, int barId, float coef,
        const float* d, float* x, const float* rhs,
        float* sp, float* sA, float* sB, bool x0_zero)
{
    const int base = gtid * NPT2;
    const bool isF = (gtid == 0);
    const bool isL = (gtid == GSIZE - 1);
    float r[NPT2], p[NPT2];
    float rl = 0.f;

    barg<GSIZE>(barId);                    // prior readers of sp region done
    if (isF) *reinterpret_cast<float2*>(sp - 2)  = make_float2(0.f, 0.f);
    if (isL) *reinterpret_cast<float2*>(sp + NN) = make_float2(0.f, 0.f);

    if (x0_zero) {
#pragma unroll
        for (int c = 0; c < NPT2; c++) { r[c] = rhs[c]; rl += r[c] * r[c]; }
    } else {
        *reinterpret_cast<float2*>(sp + base)            = make_float2(x[0], x[1]);
        *reinterpret_cast<float2*>(sp + base + NPT2 - 2) = make_float2(x[NPT2-2], x[NPT2-1]);
        barg<GSIZE>(barId);
        float2 L = *reinterpret_cast<const float2*>(sp + base - 2);
        float2 R = *reinterpret_cast<const float2*>(sp + base + NPT2);
        float w[NPT2 + 4];
        w[0] = L.x; w[1] = L.y; w[NPT2+2] = R.x; w[NPT2+3] = R.y;
#pragma unroll
        for (int c = 0; c < NPT2; c++) w[c + 2] = x[c];
        float Ax[NPT2];
#pragma unroll
        for (int c = 0; c < NPT2; c++) Ax[c] = coef * STEN5(w, c) + d[c] * x[c];
        fix_bounds<NPT2>(coef, d, x, Ax, isF, isL);
#pragma unroll
        for (int c = 0; c < NPT2; c++) { r[c] = rhs[c] - Ax[c]; rl += r[c] * r[c]; }
        barg<GSIZE>(barId);                // x-halo reads done before overwrite
    }
    *reinterpret_cast<float2*>(sp + base)            = make_float2(r[0], r[1]);
    *reinterpret_cast<float2*>(sp + base + NPT2 - 2) = make_float2(r[NPT2-2], r[NPT2-1]);
    float rs = gred<GSIZE>(rl, sB, gtid, barId);
    float2 Li = *reinterpret_cast<const float2*>(sp + base - 2);
    float2 Ri = *reinterpret_cast<const float2*>(sp + base + NPT2);
    float hl0 = Li.x, hl1 = Li.y, hr0 = Ri.x, hr1 = Ri.y;
#pragma unroll
    for (int c = 0; c < NPT2; c++) p[c] = r[c];

    for (int it = 0; it < 30; it++) {
        float w[NPT2 + 4];
        w[0] = hl0; w[1] = hl1; w[NPT2+2] = hr0; w[NPT2+3] = hr1;
#pragma unroll
        for (int c = 0; c < NPT2; c++) w[c + 2] = p[c];
        float Ap[NPT2];
#pragma unroll
        for (int c = 0; c < NPT2; c++) Ap[c] = coef * STEN5(w, c) + d[c] * p[c];
        fix_bounds<NPT2>(coef, d, p, Ap, isF, isL);
        float pl = 0.f;
#pragma unroll
        for (int c = 0; c < NPT2; c++) pl += p[c] * Ap[c];
        float pAp = gred<GSIZE>(pl, sA, gtid, barId);           // barrier 1
        float a = rs / (pAp + 1e-12f);
        float rl2 = 0.f;
#pragma unroll
        for (int c = 0; c < NPT2; c++) { r[c] -= a * Ap[c]; rl2 += r[c] * r[c]; }
        *reinterpret_cast<float2*>(sp + base)            = make_float2(r[0], r[1]);
        *reinterpret_cast<float2*>(sp + base + NPT2 - 2) = make_float2(r[NPT2-2], r[NPT2-1]);
        float rsnew = gred<GSIZE>(rl2, sB, gtid, barId);        // barrier 2
#pragma unroll
        for (int c = 0; c < NPT2; c++) x[c] += a * p[c];        // hidden by LDS
        if (rsnew < 1e-12f) break;          // == sqrt(rsnew) < 1e-6 (freeze)
        float bta = rsnew / (rs + 1e-12f);
        float2 Ln = *reinterpret_cast<const float2*>(sp + base - 2);
        float2 Rn = *reinterpret_cast<const float2*>(sp + base + NPT2);
#pragma unroll
        for (int c = 0; c < NPT2; c++) p[c] = r[c] + bta * p[c];
        hl0 = Ln.x + bta * hl0; hl1 = Ln.y + bta * hl1;
        hr0 = Rn.x + bta * hr0; hr1 = Rn.y + bta * hr1;
        rs = rsnew;
    }
}

// phase scan: 256 threads x 8 contiguous elems (in registers). ym1 = element
// before this thread's chunk (ignored for tid 0). Output ph[c] = 2pi*cumtrapz.
__device__ __forceinline__ void fast_phase(const float* y, float ym1, float halfdx,
                                           float* wsum, float* ph)
{
    int tid = threadIdx.x;
    int lane = tid & 31, wi = tid >> 5;
    float prev = ym1;
    float acc = 0.f;
#pragma unroll
    for (int c = 0; c < NP2; c++) {
        float a = (prev + y[c]) * halfdx;
        if (c == 0 && tid == 0) a = 0.f;
        acc += a;
        ph[c] = acc;
        prev = y[c];
    }
    float tot = acc, v = tot;
#pragma unroll
    for (int o = 1; o < 32; o <<= 1) {
        float n = __shfl_up_sync(0xffffffffu, v, o);
        if (lane >= o) v += n;
    }
    __syncthreads();                 // protect wsum reuse across calls
    if (lane == 31) wsum[wi] = v;
    __syncthreads();
    float off = 0.f;
    for (int j = 0; j < wi; j++) off += wsum[j];
    float excl = off + v - tot;
#pragma unroll
    for (int c = 0; c < NP2; c++) ph[c] = TWO_PI_F * (excl + ph[c]);
}

// DSMEM scalar load from cluster rank `rk`
__device__ __forceinline__ float dsmem_ldf(const float* ptr, int rk)
{
    uint32_t a = (uint32_t)__cvta_generic_to_shared(ptr);
    uint32_t ra; float v;
    asm volatile("mapa.shared::cluster.u32 %0, %1, %2;" : "=r"(ra) : "r"(a), "r"(rk));
    asm volatile("ld.shared::cluster.f32 %0, [%1];" : "=f"(v) : "r"(ra) : "memory");
    return v;
}

__device__ __forceinline__ void cluster_sync_()
{
    asm volatile("barrier.cluster.arrive.aligned;" ::: "memory");
    asm volatile("barrier.cluster.wait.aligned;"   ::: "memory");
}

// ====== ONE fused kernel: cluster of 4 CTAs = one batch; CTA = one mode =====
// Inside each CTA: group 0 (threads 0-127) solves the x system, group 1
// (threads 128-255) solves the y system concurrently via named barriers.
__global__ __launch_bounds__(NT, 1) __cluster_dims__(CL, 1, 1)
void fused_kernel(
    const float* __restrict__ s_in, const float* __restrict__ eIF,
    const float* __restrict__ xm, const float* __restrict__ ym,
    const float* __restrict__ sumx, const float* __restrict__ sumy,
    const float* __restrict__ lam, const int* __restrict__ mask,
    const float* __restrict__ initf,
    const float* __restrict__ alpha_p, const float* __restrict__ beta_p,
    const float* __restrict__ var_p, const float* __restrict__ fs_p,
    const int* __restrict__ iter_p,
    const float* __restrict__ fe_w1, const float* __restrict__ fe_b1,
    const float* __restrict__ fe_w2, const float* __restrict__ fe_b2,
    const float* __restrict__ pr_w1, const float* __restrict__ pr_b1,
    const float* __restrict__ pr_w2, const float* __restrict__ pr_b2,
    const float* __restrict__ pr_w3, const float* __restrict__ pr_b3,
    const float* __restrict__ iw_p,
    float* __restrict__ d_out)
{
    __shared__ __align__(16) float sraw0[NN + 8];  // cos -> x-CG ws -> smooth ws -> cx
    __shared__ __align__(16) float sraw1[NN + 8];  // sin -> y-CG ws -> newEIF -> cy
    __shared__ __align__(16) float brx[NN];        // rhsx -> xs
    __shared__ __align__(16) float bry[NN];        // rhsy -> ys
    __shared__ __align__(16) float u_buf[NN];
    __shared__ __align__(16) float sredA[2][16];
    __shared__ __align__(16) float sredB[2][16];
    __shared__ float wsum[8];
    __shared__ float m_avg[BB];
    __shared__ float m_h1[BB*32];
    __shared__ float m_z0[BB*18];
    __shared__ float m_z1[BB*64];
    __shared__ float m_z2[BB*32];
    __shared__ float m_res[BB*2];
    __shared__ float m_scal[4];

    float* const sbuf0 = sraw0 + 2;     // element-0 views, 2 guards each side
    float* const sbuf1 = sraw1 + 2;

    const int bkid = blockIdx.x;
    const int b     = bkid >> 2;        // batch
    const int rk    = bkid & 3;         // cluster rank == mode
    const int tid = threadIdx.x;

    const int base8 = tid * NP2;
    const int bbase = b * NN + base8;
    const int mb    = (b * KK + rk) * NN;          // this mode's row base
    const int rbase = mb + base8;
    const float alpha = *alpha_p, beta = *beta_p;
    const float varv = *var_p, fsv = *fs_p, iw = *iw_p;
    const int it_num = *iter_p;
    const bool act = (mask[b * KK + rk] != 0);
    // epilogue gather prefetch (2 elements per thread)
    const int giE0 = b * NN + rk * EN + tid;
    const int giE1 = giE0 + NT;
    const float lamE0 = lam[giE0], lamE1 = lam[giE1];
    const float sE0 = s_in[giE0],  sE1 = s_in[giE1];

    // ---------- MLP (recomputed per CTA; identical everywhere) ----------
    if (tid < BB) {
        const float* f = initf + tid * KK;
        m_avg[tid] = (((f[0] + f[1]) + f[2]) + f[3]) * 0.25f;
    }
    __syncthreads();
    {                                    // fe1: 256 outputs
        int bb = tid >> 5, j = tid & 31;
        m_h1[bb*32 + j] = fmaxf(0.f, m_avg[bb] * fe_w1[j] + fe_b1[j]);
    }
    __syncthreads();
    if (tid < 128) {                     // fe2: 128 outputs
        int bb = tid >> 4, j = tid & 15;
        float acc = fe_b2[j];
        for (int e = 0; e < 32; e++) acc += m_h1[bb*32 + e] * fe_w2[j*32 + e];
        m_z0[bb*18 + j] = fmaxf(0.f, acc);
    }
    if (tid < BB) { m_z0[tid*18 + 16] = alpha; m_z0[tid*18 + 17] = beta; }
    __syncthreads();
#pragma unroll
    for (int o = 0; o < 2; o++) {        // pr1: 512 outputs
        int idx = tid + o * NT;
        int bb = idx >> 6, j = idx & 63;
        float acc = pr_b1[j];
        for (int e = 0; e < 18; e++) acc += m_z0[bb*18 + e] * pr_w1[j*18 + e];
        m_z1[bb*64 + j] = fmaxf(0.f, acc);
    }
    __syncthreads();
    {                                    // pr2: 256 outputs
        int bb = tid >> 5, j = tid & 31;
        float acc = pr_b2[j];
        for (int e = 0; e < 64; e++) acc += m_z1[bb*64 + e] * pr_w2[j*64 + e];
        m_z2[bb*32 + j] = fmaxf(0.f, acc);
    }
    __syncthreads();
    if (tid < 16) {                      // pr3: 16 outputs
        int bb = tid >> 1, j = tid & 1;
        float acc = pr_b3[j];
        for (int e = 0; e < 32; e++) acc += m_z2[bb*32 + e] * pr_w3[j*32 + e];
        m_res[bb*2 + j] = tanhf(acc);
    }
    __syncthreads();
    if (tid == 0) {
        float fac = 1.f / (1.f + expf(-iw * (float)it_num));
        float m0 = 0.f, m1 = 0.f;
        for (int bb = 0; bb < BB; bb++) {
            m0 += (m_res[bb*2 + 0] * fac * 0.1f) * alpha;
            m1 += (m_res[bb*2 + 1] * fac * 0.1f) * beta;
        }
        m0 *= 0.125f; m1 *= 0.125f;
        float na = fminf(fmaxf(alpha + m0, 1e-6f), 0.01f);
        float nb = fminf(fmaxf(beta  + m1, 1e-6f), 0.1f);
        double bt = pow(10.0, (double)it_num / 36.0 - 10.0);
        float betathr = fminf((float)bt, nb);
        m_scal[0] = na; m_scal[1] = nb;
        m_scal[2] = 2.f / na; m_scal[3] = 2.f / betathr;
        if (bkid == 0) { d_out[OUT_SC + 0] = na; d_out[OUT_SC + 1] = nb; }
    }
    __syncthreads();
    const float na = m_scal[0];
    const float coefA = m_scal[2];
    const float coefS = m_scal[3];
    const float dxf = 1.0f / fsv;
    const float halfdx = 0.5f * dxf;

    // ---------- u = projec5(...) ----------
    {
        float loc = 0.f;
        float v8[NP2];
#pragma unroll
        for (int q = 0; q < NP2/4; q++) {
            float4 a = *reinterpret_cast<const float4*>(s_in + bbase + 4*q);
            float4 bq = *reinterpret_cast<const float4*>(sumx + bbase + 4*q);
            float4 cq = *reinterpret_cast<const float4*>(sumy + bbase + 4*q);
            float4 eq = *reinterpret_cast<const float4*>(lam  + bbase + 4*q);
            float t0 = a.x - bq.x - cq.x - eq.x / na;
            float t1 = a.y - bq.y - cq.y - eq.y / na;
            float t2 = a.z - bq.z - cq.z - eq.z / na;
            float t3 = a.w - bq.w - cq.w - eq.w / na;
            v8[4*q+0] = t0; v8[4*q+1] = t1; v8[4*q+2] = t2; v8[4*q+3] = t3;
            loc += t0*t0 + t1*t1 + t2*t2 + t3*t3;
        }
        float n2 = gred<NT>(loc, sredA[0], tid, 0);
        float n = sqrtf(n2);
        float e = sqrtf((float)NN * varv);
        float scale = (n > e) ? (e / fmaxf(n, 1e-30f)) : 1.f;
#pragma unroll
        for (int c = 0; c < NP2; c++) u_buf[base8 + c] = v8[c] * scale;
    }

    // ---------- phase + trig/rhs into SMEM ----------
    {
        float eifr[NP2];
#pragma unroll
        for (int q = 0; q < NP2/4; q++) {
            float4 t = *reinterpret_cast<const float4*>(eIF + rbase + 4*q);
            eifr[4*q+0] = t.x; eifr[4*q+1] = t.y; eifr[4*q+2] = t.z; eifr[4*q+3] = t.w;
        }
        float eifm1 = (tid > 0) ? eIF[rbase - 1] : 0.f;
        float ph[NP2];
        fast_phase(eifr, eifm1, halfdx, wsum, ph);
#pragma unroll
        for (int q = 0; q < NP2/4; q++) {
            float4 a = *reinterpret_cast<const float4*>(s_in + bbase + 4*q);
            float4 bq = *reinterpret_cast<const float4*>(sumx + bbase + 4*q);
            float4 cq = *reinterpret_cast<const float4*>(sumy + bbase + 4*q);
            float4 eq = *reinterpret_cast<const float4*>(lam  + bbase + 4*q);
            float4 xq = *reinterpret_cast<const float4*>(xm + rbase + 4*q);
            float4 yq = *reinterpret_cast<const float4*>(ym + rbase + 4*q);
#pragma unroll
            for (int j = 0; j < 4; j++) {
                int c = 4*q + j;
                int i = base8 + c;
                float ssn, ccs;
                sincosf(ph[c], &ssn, &ccs);
                float xv = ((const float*)&xq.x)[j];
                float yv = ((const float*)&yq.x)[j];
                float resid = ((const float*)&a.x)[j]
                            - (((const float*)&bq.x)[j] - xv * ccs)
                            - (((const float*)&cq.x)[j] - yv * ssn)
                            - u_buf[i]
                            - ((const float*)&eq.x)[j] / na;
                sbuf0[i] = ccs;
                sbuf1[i] = ssn;
                brx[i] = ccs * resid;
                bry[i] = ssn * resid;
            }
        }
    }
    __syncthreads();

    // ---------- concurrent CG: group 0 = x system, group 1 = y system ------
    {
        const int grp = tid >> 7;           // 0 or 1
        const int gtid = tid & (GT - 1);
        const int barId = 1 + grp;
        const float* trig = grp ? sbuf1 : sbuf0;
        const float* rh   = grp ? bry   : brx;
        const float* x0g  = (grp ? ym : xm) + mb;
        float* sp         = grp ? sbuf1 : sbuf0;
        float* outb       = grp ? bry : brx;
        float* sA         = sredA[grp];
        float* sB         = sredB[grp];

        float d16[NPT], rhs16[NPT], x16[NPT];
        const int gb = gtid * NPT;
#pragma unroll
        for (int q = 0; q < NPT/4; q++) {
            float4 xq = *reinterpret_cast<const float4*>(x0g + gb + 4*q);
#pragma unroll
            for (int j = 0; j < 4; j++) {
                int c = 4*q + j;
                float t = trig[gb + c];
                d16[c] = t * t + 1e-6f;
                rhs16[c] = rh[gb + c];
                x16[c] = ((const float*)&xq.x)[j];
            }
        }
        cg_solve<GT, NPT>(gtid, barId, coefA, d16, x16, rhs16, sp, sA, sB, false);
        barg<GT>(barId);                 // group CG traffic complete
#pragma unroll
        for (int c = 0; c < NPT; c++) outb[gb + c] = x16[c];
    }
    __syncthreads();                     // both solutions visible to all

    // ---------- deltaIF + smooth CG (full 256-thread block, NPT=8) --------
    float sx8[NP2];
    {
        float srhs[NP2], sd[NP2];
#pragma unroll
        for (int c = 0; c < NP2; c++) {
            int i = base8 + c;
            float xb, yb;
            if (i == 0) {
                xb = (brx[1] - brx[0]) / dxf;
                yb = (bry[1] - bry[0]) / dxf;
            } else if (i == NN - 1) {
                xb = (brx[NN-1] - brx[NN-2]) / dxf;
                yb = (bry[NN-1] - bry[NN-2]) / dxf;
            } else {
                xb = (brx[i+1] - brx[i-1]) / (2.0f * dxf);
                yb = (bry[i+1] - bry[i-1]) / (2.0f * dxf);
            }
            float xv = brx[i], yv = bry[i];
            float denom = xv * xv + yv * yv + 1e-12f;
            srhs[c] = (xv * yb - yv * xb) / (denom * TWO_PI_F);
            sd[c] = 1.0f + 1e-6f;
            sx8[c] = 0.f;
        }
        cg_solve<NT, NP2>(tid, 0, coefS, sd, sx8, srhs, sbuf0, sredA[0], sredB[0], true);
        __syncthreads();   // CG trailing SMEM traffic complete before reuse
    }

    // ---------- outputs eIF/xm/ym + stash new_eIF ----------
    float ne8[NP2];
#pragma unroll
    for (int c = 0; c < NP2; c++) {
        int i = base8 + c;
        int gi = mb + i;
        float e = eIF[gi];
        ne8[c] = act ? (e - 0.5f * sx8[c]) : e;
        d_out[OUT_EIF + gi] = ne8[c];
        d_out[OUT_XM  + gi] = act ? brx[i] : xm[gi];
        d_out[OUT_YM  + gi] = act ? bry[i] : ym[gi];
        sbuf1[i] = ne8[c];
    }
    __syncthreads();

    // ---------- new phase + masked contributions into sbuf0/sbuf1 ----------
    {
        float nem1 = (tid > 0) ? sbuf1[base8 - 1] : 0.f;
        float ph[NP2];
        fast_phase(ne8, nem1, halfdx, wsum, ph);
        float cx[NP2], cy[NP2];
#pragma unroll
        for (int c = 0; c < NP2; c++) {
            float ssn, ccs;
            sincosf(ph[c], &ssn, &ccs);
            int i = base8 + c;
            cx[c] = act ? brx[i] * ccs : 0.f;
            cy[c] = act ? bry[i] * ssn : 0.f;
        }
        __syncthreads();        // all reads of sbuf1 (nem1) complete
#pragma unroll
        for (int c = 0; c < NP2; c++) {
            sbuf0[base8 + c] = cx[c];
            sbuf1[base8 + c] = cy[c];
        }
    }

    // ---------- cluster gather: bsx/bsy + lamuda ----------
    cluster_sync_();
    {
        int i0 = rk * EN + tid;
        int i1 = i0 + NT;
        float bsx0 = 0.f, bsy0 = 0.f, bsx1 = 0.f, bsy1 = 0.f;
#pragma unroll
        for (int k = 0; k < KK; k++) {
            bsx0 += dsmem_ldf(&sbuf0[i0], k);
            bsy0 += dsmem_ldf(&sbuf1[i0], k);
            bsx1 += dsmem_ldf(&sbuf0[i1], k);
            bsy1 += dsmem_ldf(&sbuf1[i1], k);
        }
        d_out[OUT_BSX + giE0] = bsx0;
        d_out[OUT_BSY + giE0] = bsy0;
        d_out[OUT_LAM + giE0] = lamE0 + na * (u_buf[i0] + bsx0 + bsy0 - sE0);
        d_out[OUT_BSX + giE1] = bsx1;
        d_out[OUT_BSY + giE1] = bsy1;
        d_out[OUT_LAM + giE1] = lamE1 + na * (u_buf[i1] + bsx1 + bsy1 - sE1);
    }
    cluster_sync_();
}

// ---------------- launch ---------------------------------------------------
extern "C" void kernel_launch(void* const* d_in, const int* in_sizes, int n_in,
                              void* d_out_v, int out_size)
{
    const float* s      = (const float*)d_in[0];
    const float* eIF    = (const float*)d_in[1];
    const float* xm     = (const float*)d_in[2];
    const float* ym     = (const float*)d_in[3];
    const float* sum_x  = (const float*)d_in[4];
    const float* sum_y  = (const float*)d_in[5];
    const float* lamuda = (const float*)d_in[6];
    const float* initf  = (const float*)d_in[7];
    const int*   mmask  = (const int*)  d_in[8];
    const float* alpha  = (const float*)d_in[9];
    const float* beta   = (const float*)d_in[10];
    const float* var    = (const float*)d_in[11];
    const float* fs     = (const float*)d_in[12];
    const int*   iter   = (const int*)  d_in[13];
    const float* fe_w1  = (const float*)d_in[14];
    const float* fe_b1  = (const float*)d_in[15];
    const float* fe_w2  = (const float*)d_in[16];
    const float* fe_b2  = (const float*)d_in[17];
    const float* pr_w1  = (const float*)d_in[18];
    const float* pr_b1  = (const float*)d_in[19];
    const float* pr_w2  = (const float*)d_in[20];
    const float* pr_b2  = (const float*)d_in[21];
    const float* pr_w3  = (const float*)d_in[22];
    const float* pr_b3  = (const float*)d_in[23];
    const float* iw     = (const float*)d_in[24];
    float* d_out = (float*)d_out_v;

    fused_kernel<<<NGRID, NT>>>(s, eIF, xm, ym, sum_x, sum_y, lamuda, mmask,
                                initf, alpha, beta, var, fs, iter,
                                fe_w1, fe_b1, fe_w2, fe_b2,
                                pr_w1, pr_b1, pr_w2, pr_b2, pr_w3, pr_b3,
                                iw, d_out);
}

// round 15
// speedup vs baseline: 1.7850x; 1.7850x over previous
#include <cuda_runtime.h>
#include <math.h>
#include <stdint.h>

// ---------------- problem constants ----------------
#define NN   2048
#define NT   128                // threads per CTA
#define NPT  16                 // elements per thread (NN/NT)
#define NH   8                  // float2 pairs per thread
#define BB   8
#define KK   4
#define CL   8                  // cluster size: 4 modes x {x,y}
#define NGRID (BB * CL)         // 64 CTAs
#define EN   (NN / CL)          // 256 elements per rank in epilogue gather
#define TWO_PI_F 6.283185307179586f

// output layout (flattened tuple, fp32)
#define OUT_EIF 0
#define OUT_XM  65536
#define OUT_YM  131072
#define OUT_BSX 196608
#define OUT_BSY 212992
#define OUT_LAM 229376
#define OUT_SC  245760

// ---------------- packed f32x2 helpers (sm_103a) ----------------
__device__ __forceinline__ float2 ffma2(float2 a, float2 b, float2 c)
{
    float2 d;
    asm("fma.rn.f32x2 %0, %1, %2, %3;"
        : "=l"(reinterpret_cast<unsigned long long&>(d))
        : "l"(reinterpret_cast<unsigned long long&>(a)),
          "l"(reinterpret_cast<unsigned long long&>(b)),
          "l"(reinterpret_cast<unsigned long long&>(c)));
    return d;
}
__device__ __forceinline__ float2 fmul2(float2 a, float2 b)
{
    float2 d;
    asm("mul.rn.f32x2 %0, %1, %2;"
        : "=l"(reinterpret_cast<unsigned long long&>(d))
        : "l"(reinterpret_cast<unsigned long long&>(a)),
          "l"(reinterpret_cast<unsigned long long&>(b)));
    return d;
}

// block reduce over 128 threads: 3 shuffles (8-lane groups) -> 16 partials ->
// 1 barrier -> every thread sums 4x float4.
__device__ __forceinline__ float bred(float v, float* sred, int tid)
{
#pragma unroll
    for (int o = 4; o > 0; o >>= 1) v += __shfl_down_sync(0xffffffffu, v, o);
    if ((tid & 7) == 0) sred[tid >> 3] = v;
    __syncthreads();
    float4 q0 = reinterpret_cast<float4*>(sred)[0];
    float4 q1 = reinterpret_cast<float4*>(sred)[1];
    float4 q2 = reinterpret_cast<float4*>(sred)[2];
    float4 q3 = reinterpret_cast<float4*>(sred)[3];
    float s0 = (q0.x + q0.y) + (q0.z + q0.w);
    float s1 = (q1.x + q1.y) + (q1.z + q1.w);
    float s2 = (q2.x + q2.y) + (q2.z + q2.w);
    float s3 = (q3.x + q3.y) + (q3.z + q3.w);
    return (s0 + s1) + (s2 + s3);
}

// interior 5-point stencil of (D^T D): [1,-4,6,-4,1]; w[k] = elem(base-2+k)
#define STEN5(w, c) ((w)[c] - 4.f*(w)[(c)+1] + 6.f*(w)[(c)+2] - 4.f*(w)[(c)+3] + (w)[(c)+4])

// Boundary rows, exact reference expressions, recomputed on edge threads only.
__device__ __forceinline__ void fix_bounds(float coef, const float* d,
                                           const float* v, float* Av,
                                           bool isF, bool isL)
{
    if (isF) {
        Av[0] = coef * (2.f*v[0] - 3.f*v[1] + v[2]) + d[0]*v[0];
        Av[1] = coef * (-3.f*v[0] + 6.f*v[1] - 4.f*v[2] + v[3]) + d[1]*v[1];
    }
    if (isL) {
        Av[NPT-2] = coef * (v[NPT-4] - 4.f*v[NPT-3] + 6.f*v[NPT-2] - 3.f*v[NPT-1])
                  + d[NPT-2]*v[NPT-2];
        Av[NPT-1] = coef * (v[NPT-3] - 3.f*v[NPT-2] + 2.f*v[NPT-1])
                  + d[NPT-1]*v[NPT-1];
    }
}

// 128-thread CG, NPT=16, reference semantics: explicit rsnew = ||r-a*Ap||^2,
// freeze == break. p in registers (packed float2); r halos via SMEM float2;
// neighbor p halos reconstructed as r_halo + beta*p_halo_old. sp = element-0
// view with 2 guard floats each side (zeroed; never used by boundary math).
// 2 barriers/iter. Inner loop uses fma.rn.f32x2 packed arithmetic (per-lane
// IEEE identical to the scalar version; only dot accumulation order differs).
__device__ __forceinline__ void cg_solve(int tid, float coef,
        const float* d, float* x, const float* rhs,
        float* sp, float* sA, float* sB, bool x0_zero)
{
    const int base = tid * NPT;
    const bool isF = (tid == 0);
    const bool isL = (tid == NT - 1);
    float r[NPT];
    float rl = 0.f;

    __syncthreads();                       // prior readers of sp region done
    if (isF) *reinterpret_cast<float2*>(sp - 2)  = make_float2(0.f, 0.f);
    if (isL) *reinterpret_cast<float2*>(sp + NN) = make_float2(0.f, 0.f);

    if (x0_zero) {
#pragma unroll
        for (int c = 0; c < NPT; c++) { r[c] = rhs[c]; rl += r[c] * r[c]; }
    } else {
        *reinterpret_cast<float2*>(sp + base)           = make_float2(x[0], x[1]);
        *reinterpret_cast<float2*>(sp + base + NPT - 2) = make_float2(x[NPT-2], x[NPT-1]);
        __syncthreads();
        float2 L = *reinterpret_cast<const float2*>(sp + base - 2);
        float2 R = *reinterpret_cast<const float2*>(sp + base + NPT);
        float w[NPT + 4];
        w[0] = L.x; w[1] = L.y; w[NPT+2] = R.x; w[NPT+3] = R.y;
#pragma unroll
        for (int c = 0; c < NPT; c++) w[c + 2] = x[c];
        float Ax[NPT];
#pragma unroll
        for (int c = 0; c < NPT; c++) Ax[c] = coef * STEN5(w, c) + d[c] * x[c];
        fix_bounds(coef, d, x, Ax, isF, isL);
#pragma unroll
        for (int c = 0; c < NPT; c++) { r[c] = rhs[c] - Ax[c]; rl += r[c] * r[c]; }
        __syncthreads();                   // x-halo reads done before overwrite
    }
    *reinterpret_cast<float2*>(sp + base)           = make_float2(r[0], r[1]);
    *reinterpret_cast<float2*>(sp + base + NPT - 2) = make_float2(r[NPT-2], r[NPT-1]);
    float rs = bred(rl, sB, tid);
    float2 Li = *reinterpret_cast<const float2*>(sp + base - 2);
    float2 Ri = *reinterpret_cast<const float2*>(sp + base + NPT);
    float hl0 = Li.x, hl1 = Li.y, hr0 = Ri.x, hr1 = Ri.y;

    // pack state into float2 pairs (register-aliasing; free)
    float2 r2[NH], p2[NH], x2[NH], d2[NH];
#pragma unroll
    for (int j = 0; j < NH; j++) {
        r2[j] = make_float2(r[2*j], r[2*j+1]);
        p2[j] = r2[j];
        x2[j] = make_float2(x[2*j], x[2*j+1]);
        d2[j] = make_float2(d[2*j], d[2*j+1]);
    }
    const float2 coef2 = make_float2(coef, coef);

    for (int it = 0; it < 30; it++) {
        float w[NPT + 4];
        w[0] = hl0; w[1] = hl1; w[NPT+2] = hr0; w[NPT+3] = hr1;
#pragma unroll
        for (int j = 0; j < NH; j++) { w[2*j+2] = p2[j].x; w[2*j+3] = p2[j].y; }
        float2 Ap2[NH];
#pragma unroll
        for (int j = 0; j < NH; j++) {
            float s0 = STEN5(w, 2*j);
            float s1 = STEN5(w, 2*j + 1);
            Ap2[j] = ffma2(d2[j], p2[j], fmul2(coef2, make_float2(s0, s1)));
        }
        if (isF || isL) {       // exact boundary-row recompute on edge threads
            float pv[NPT], dv[NPT], Av[NPT];
#pragma unroll
            for (int j = 0; j < NH; j++) {
                pv[2*j] = p2[j].x; pv[2*j+1] = p2[j].y;
                dv[2*j] = d2[j].x; dv[2*j+1] = d2[j].y;
                Av[2*j] = Ap2[j].x; Av[2*j+1] = Ap2[j].y;
            }
            fix_bounds(coef, dv, pv, Av, isF, isL);
            Ap2[0] = make_float2(Av[0], Av[1]);
            Ap2[NH-1] = make_float2(Av[NPT-2], Av[NPT-1]);
        }
        float2 pacc = make_float2(0.f, 0.f);
#pragma unroll
        for (int j = 0; j < NH; j++) pacc = ffma2(p2[j], Ap2[j], pacc);
        float pAp = bred(pacc.x + pacc.y, sA, tid);             // barrier 1
        float a = rs / (pAp + 1e-12f);
        const float2 na2 = make_float2(-a, -a);
        float2 racc = make_float2(0.f, 0.f);
#pragma unroll
        for (int j = 0; j < NH; j++) {
            r2[j] = ffma2(na2, Ap2[j], r2[j]);
            racc = ffma2(r2[j], r2[j], racc);
        }
        *reinterpret_cast<float2*>(sp + base)           = r2[0];
        *reinterpret_cast<float2*>(sp + base + NPT - 2) = r2[NH-1];
        float rsnew = bred(racc.x + racc.y, sB, tid);           // barrier 2
        const float2 a2 = make_float2(a, a);
#pragma unroll
        for (int j = 0; j < NH; j++) x2[j] = ffma2(a2, p2[j], x2[j]);  // hidden
        if (rsnew < 1e-12f) break;          // == sqrt(rsnew) < 1e-6 (freeze)
        float bta = rsnew / (rs + 1e-12f);
        const float2 b2 = make_float2(bta, bta);
        float2 Ln = *reinterpret_cast<const float2*>(sp + base - 2);
        float2 Rn = *reinterpret_cast<const float2*>(sp + base + NPT);
#pragma unroll
        for (int j = 0; j < NH; j++) p2[j] = ffma2(b2, p2[j], r2[j]);
        hl0 = Ln.x + bta * hl0; hl1 = Ln.y + bta * hl1;
        hr0 = Rn.x + bta * hr0; hr1 = Rn.y + bta * hr1;
        rs = rsnew;
    }
#pragma unroll
    for (int j = 0; j < NH; j++) { x[2*j] = x2[j].x; x[2*j+1] = x2[j].y; }
}

// phase scan: 128 threads x 16 contiguous elems (in registers). ym1 = element
// before this thread's chunk (ignored for tid 0). Output ph[c] = 2pi*cumtrapz.
__device__ __forceinline__ void fast_phase(const float* y, float ym1, float halfdx,
                                           float* wsum, float* ph)
{
    int tid = threadIdx.x;
    int lane = tid & 31, wi = tid >> 5;
    float prev = ym1;
    float acc = 0.f;
#pragma unroll
    for (int c = 0; c < NPT; c++) {
        float a = (prev + y[c]) * halfdx;
        if (c == 0 && tid == 0) a = 0.f;
        acc += a;
        ph[c] = acc;
        prev = y[c];
    }
    float tot = acc, v = tot;
#pragma unroll
    for (int o = 1; o < 32; o <<= 1) {
        float n = __shfl_up_sync(0xffffffffu, v, o);
        if (lane >= o) v += n;
    }
    __syncthreads();                 // protect wsum reuse across calls
    if (lane == 31) wsum[wi] = v;
    __syncthreads();
    float off = 0.f;
    for (int j = 0; j < wi; j++) off += wsum[j];
    float excl = off + v - tot;
#pragma unroll
    for (int c = 0; c < NPT; c++) ph[c] = TWO_PI_F * (excl + ph[c]);
}

// DSMEM scalar load from cluster rank `rk`
__device__ __forceinline__ float dsmem_ldf(const float* ptr, int rk)
{
    uint32_t a = (uint32_t)__cvta_generic_to_shared(ptr);
    uint32_t ra; float v;
    asm volatile("mapa.shared::cluster.u32 %0, %1, %2;" : "=r"(ra) : "r"(a), "r"(rk));
    asm volatile("ld.shared::cluster.f32 %0, [%1];" : "=f"(v) : "r"(ra) : "memory");
    return v;
}

__device__ __forceinline__ void cluster_sync_()
{
    asm volatile("barrier.cluster.arrive.aligned;" ::: "memory");
    asm volatile("barrier.cluster.wait.aligned;"   ::: "memory");
}

// ====== ONE fused kernel: cluster of 8 CTAs = one batch (4 modes x {x,y}) ===
__global__ __launch_bounds__(NT, 1) __cluster_dims__(CL, 1, 1)
void fused_kernel(
    const float* __restrict__ s_in, const float* __restrict__ eIF,
    const float* __restrict__ xm, const float* __restrict__ ym,
    const float* __restrict__ sumx, const float* __restrict__ sumy,
    const float* __restrict__ lam, const int* __restrict__ mask,
    const float* __restrict__ initf,
    const float* __restrict__ alpha_p, const float* __restrict__ beta_p,
    const float* __restrict__ var_p, const float* __restrict__ fs_p,
    const int* __restrict__ iter_p,
    const float* __restrict__ fe_w1, const float* __restrict__ fe_b1,
    const float* __restrict__ fe_w2, const float* __restrict__ fe_b2,
    const float* __restrict__ pr_w1, const float* __restrict__ pr_b1,
    const float* __restrict__ pr_w2, const float* __restrict__ pr_b2,
    const float* __restrict__ pr_w3, const float* __restrict__ pr_b3,
    const float* __restrict__ iw_p,
    float* __restrict__ d_out)
{
    __shared__ __align__(16) float sraw0[NN + 8];  // CG workspace / contribution
    __shared__ __align__(16) float sraw1[NN + 8];  // new_eIF stash
    __shared__ __align__(16) float own[NN];        // own CG solution
    __shared__ __align__(16) float peer[NN];       // peer CG solution (DSMEM copy)
    __shared__ __align__(16) float u_buf[NN];
    __shared__ __align__(16) float sredA[16];
    __shared__ __align__(16) float sredB[16];
    __shared__ float wsum[4];
    __shared__ float m_avg[BB];
    __shared__ float m_h1[BB*32];
    __shared__ float m_z0[BB*18];
    __shared__ float m_z1[BB*64];
    __shared__ float m_z2[BB*32];
    __shared__ float m_res[BB*2];
    __shared__ float m_scal[4];

    float* const sbuf0 = sraw0 + 2;     // element-0 views, 2 guards each side
    float* const sbuf1 = sraw1 + 2;

    const int bkid = blockIdx.x;
    const int b     = bkid >> 3;        // batch
    const int rk    = bkid & 7;         // cluster rank
    const int kmode = rk >> 1;          // mode 0..3
    const int which = rk & 1;           // 0 = x-solve, 1 = y-solve
    const int tid = threadIdx.x;

    const int base16 = tid * NPT;
    const int bbase = b * NN + base16;
    const int mb    = (b * KK + kmode) * NN;       // this mode's row base
    const int rbase = mb + base16;
    const float alpha = *alpha_p, beta = *beta_p;
    const float varv = *var_p, fsv = *fs_p, iw = *iw_p;
    const int it_num = *iter_p;
    const bool act = (mask[b * KK + kmode] != 0);
    // epilogue gather prefetch (2 elements per thread)
    const int giE0 = b * NN + rk * EN + tid;
    const int giE1 = giE0 + NT;
    const float lamE0 = lam[giE0], lamE1 = lam[giE1];
    const float sE0 = s_in[giE0],  sE1 = s_in[giE1];

    // ---------- MLP (recomputed per CTA; identical everywhere) ----------
    if (tid < BB) {
        const float* f = initf + tid * KK;
        m_avg[tid] = (((f[0] + f[1]) + f[2]) + f[3]) * 0.25f;
    }
    __syncthreads();
#pragma unroll
    for (int o = 0; o < 2; o++) {       // fe1: 256 outputs
        int idx = tid + o * NT;
        int bb = idx >> 5, j = idx & 31;
        m_h1[bb*32 + j] = fmaxf(0.f, m_avg[bb] * fe_w1[j] + fe_b1[j]);
    }
    __syncthreads();
    {                                    // fe2: 128 outputs
        int bb = tid >> 4, j = tid & 15;
        float acc = fe_b2[j];
        for (int e = 0; e < 32; e++) acc += m_h1[bb*32 + e] * fe_w2[j*32 + e];
        m_z0[bb*18 + j] = fmaxf(0.f, acc);
    }
    if (tid < BB) { m_z0[tid*18 + 16] = alpha; m_z0[tid*18 + 17] = beta; }
    __syncthreads();
#pragma unroll
    for (int o = 0; o < 4; o++) {       // pr1: 512 outputs
        int idx = tid + o * NT;
        int bb = idx >> 6, j = idx & 63;
        float acc = pr_b1[j];
        for (int e = 0; e < 18; e++) acc += m_z0[bb*18 + e] * pr_w1[j*18 + e];
        m_z1[bb*64 + j] = fmaxf(0.f, acc);
    }
    __syncthreads();
#pragma unroll
    for (int o = 0; o < 2; o++) {       // pr2: 256 outputs
        int idx = tid + o * NT;
        int bb = idx >> 5, j = idx & 31;
        float acc = pr_b2[j];
        for (int e = 0; e < 64; e++) acc += m_z1[bb*64 + e] * pr_w2[j*64 + e];
        m_z2[bb*32 + j] = fmaxf(0.f, acc);
    }
    __syncthreads();
    if (tid < 16) {                      // pr3: 16 outputs
        int bb = tid >> 1, j = tid & 1;
        float acc = pr_b3[j];
        for (int e = 0; e < 32; e++) acc += m_z2[bb*32 + e] * pr_w3[j*32 + e];
        m_res[bb*2 + j] = tanhf(acc);
    }
    __syncthreads();
    if (tid == 0) {
        float fac = 1.f / (1.f + expf(-iw * (float)it_num));
        float m0 = 0.f, m1 = 0.f;
        for (int bb = 0; bb < BB; bb++) {
            m0 += (m_res[bb*2 + 0] * fac * 0.1f) * alpha;
            m1 += (m_res[bb*2 + 1] * fac * 0.1f) * beta;
        }
        m0 *= 0.125f; m1 *= 0.125f;
        float na = fminf(fmaxf(alpha + m0, 1e-6f), 0.01f);
        float nb = fminf(fmaxf(beta  + m1, 1e-6f), 0.1f);
        double bt = pow(10.0, (double)it_num / 36.0 - 10.0);
        float betathr = fminf((float)bt, nb);
        m_scal[0] = na; m_scal[1] = nb;
        m_scal[2] = 2.f / na; m_scal[3] = 2.f / betathr;
        if (bkid == 0) { d_out[OUT_SC + 0] = na; d_out[OUT_SC + 1] = nb; }
    }
    __syncthreads();
    const float na = m_scal[0];
    const float coefA = m_scal[2];
    const float coefS = m_scal[3];
    const float dxf = 1.0f / fsv;
    const float halfdx = 0.5f * dxf;

    // ---------- u = projec5(...) ----------
    {
        float loc = 0.f;
        float v16[NPT];
#pragma unroll
        for (int q = 0; q < NPT/4; q++) {
            float4 a = *reinterpret_cast<const float4*>(s_in + bbase + 4*q);
            float4 bq = *reinterpret_cast<const float4*>(sumx + bbase + 4*q);
            float4 cq = *reinterpret_cast<const float4*>(sumy + bbase + 4*q);
            float4 eq = *reinterpret_cast<const float4*>(lam  + bbase + 4*q);
            float t0 = a.x - bq.x - cq.x - eq.x / na;
            float t1 = a.y - bq.y - cq.y - eq.y / na;
            float t2 = a.z - bq.z - cq.z - eq.z / na;
            float t3 = a.w - bq.w - cq.w - eq.w / na;
            v16[4*q+0] = t0; v16[4*q+1] = t1; v16[4*q+2] = t2; v16[4*q+3] = t3;
            loc += t0*t0 + t1*t1 + t2*t2 + t3*t3;
        }
        float n2 = bred(loc, sredA, tid);
        float n = sqrtf(n2);
        float e = sqrtf((float)NN * varv);
        float scale = (n > e) ? (e / fmaxf(n, 1e-30f)) : 1.f;
#pragma unroll
        for (int c = 0; c < NPT; c++) u_buf[base16 + c] = v16[c] * scale;
    }

    // ---------- phase + rhs/diag/x0 (registers) ----------
    float d16[NPT], rhs16[NPT], x16[NPT];
    {
        float eifr[NPT];
#pragma unroll
        for (int q = 0; q < NPT/4; q++) {
            float4 t = *reinterpret_cast<const float4*>(eIF + rbase + 4*q);
            eifr[4*q+0] = t.x; eifr[4*q+1] = t.y; eifr[4*q+2] = t.z; eifr[4*q+3] = t.w;
        }
        float eifm1 = (tid > 0) ? eIF[rbase - 1] : 0.f;
        float ph[NPT];
        fast_phase(eifr, eifm1, halfdx, wsum, ph);
#pragma unroll
        for (int q = 0; q < NPT/4; q++) {
            float4 a = *reinterpret_cast<const float4*>(s_in + bbase + 4*q);
            float4 bq = *reinterpret_cast<const float4*>(sumx + bbase + 4*q);
            float4 cq = *reinterpret_cast<const float4*>(sumy + bbase + 4*q);
            float4 eq = *reinterpret_cast<const float4*>(lam  + bbase + 4*q);
            float4 xq = *reinterpret_cast<const float4*>(xm + rbase + 4*q);
            float4 yq = *reinterpret_cast<const float4*>(ym + rbase + 4*q);
#pragma unroll
            for (int j = 0; j < 4; j++) {
                int c = 4*q + j;
                float ssn, ccs;
                sincosf(ph[c], &ssn, &ccs);
                float xv = ((const float*)&xq.x)[j];
                float yv = ((const float*)&yq.x)[j];
                float resid = ((const float*)&a.x)[j]
                            - (((const float*)&bq.x)[j] - xv * ccs)
                            - (((const float*)&cq.x)[j] - yv * ssn)
                            - u_buf[base16 + c]
                            - ((const float*)&eq.x)[j] / na;
                float t = which ? ssn : ccs;
                d16[c] = t * t + 1e-6f;
                rhs16[c] = t * resid;
                x16[c] = which ? yv : xv;
            }
        }
    }

    // ---------- this CTA's CG solve (x OR y system) ----------
    cg_solve(tid, coefA, d16, x16, rhs16, sbuf0, sredA, sredB, false);
    __syncthreads();       // CG trailing SMEM traffic complete
#pragma unroll
    for (int c = 0; c < NPT; c++) own[base16 + c] = x16[c];
    __syncthreads();

    // ---------- exchange with paired CTA (rank ^ 1) via DSMEM ----------
    cluster_sync_();
    {
        const int prk = rk ^ 1;
#pragma unroll
        for (int c = 0; c < NPT; c++)
            peer[base16 + c] = dsmem_ldf(&own[base16 + c], prk);
    }
    const float* xsP = which ? peer : own;
    const float* ysP = which ? own : peer;

    // ---------- deltaIF + smooth CG (duplicated across the pair) ----------
    float sx16[NPT];
    {
        float srhs[NPT], sd[NPT];
        __syncthreads();       // peer[] fully written before neighbor reads
#pragma unroll
        for (int c = 0; c < NPT; c++) {
            int i = base16 + c;
            float xb, yb;
            if (i == 0) {
                xb = (xsP[1] - xsP[0]) / dxf;
                yb = (ysP[1] - ysP[0]) / dxf;
            } else if (i == NN - 1) {
                xb = (xsP[NN-1] - xsP[NN-2]) / dxf;
                yb = (ysP[NN-1] - ysP[NN-2]) / dxf;
            } else {
                xb = (xsP[i+1] - xsP[i-1]) / (2.0f * dxf);
                yb = (ysP[i+1] - ysP[i-1]) / (2.0f * dxf);
            }
            float xv = xsP[i], yv = ysP[i];
            float denom = xv * xv + yv * yv + 1e-12f;
            srhs[c] = (xv * yb - yv * xb) / (denom * TWO_PI_F);
            sd[c] = 1.0f + 1e-6f;
            sx16[c] = 0.f;
        }
        cg_solve(tid, coefS, sd, sx16, srhs, sbuf0, sredA, sredB, true);
        __syncthreads();   // CG trailing SMEM traffic complete before reuse
    }

    // ---------- outputs eIF/xm(/ym) + stash new_eIF ----------
    float ne16[NPT];
#pragma unroll
    for (int c = 0; c < NPT; c++) {
        int i = base16 + c;
        int gi = mb + i;
        float e = eIF[gi];
        ne16[c] = act ? (e - 0.5f * sx16[c]) : e;
        if (which == 0) {
            d_out[OUT_EIF + gi] = ne16[c];
            d_out[OUT_XM  + gi] = act ? xsP[i] : xm[gi];
        } else {
            d_out[OUT_YM  + gi] = act ? ysP[i] : ym[gi];
        }
        sbuf1[i] = ne16[c];
    }
    __syncthreads();

    // ---------- new phase + masked contribution into sbuf0 ----------
    {
        float nem1 = (tid > 0) ? sbuf1[base16 - 1] : 0.f;
        float ph[NPT];
        fast_phase(ne16, nem1, halfdx, wsum, ph);
        float cc[NPT];
#pragma unroll
        for (int c = 0; c < NPT; c++) {
            float ssn, ccs;
            sincosf(ph[c], &ssn, &ccs);
            int i = base16 + c;
            cc[c] = act ? (which ? ysP[i] * ssn : xsP[i] * ccs) : 0.f;
        }
        __syncthreads();
#pragma unroll
        for (int c = 0; c < NPT; c++) sbuf0[base16 + c] = cc[c];
    }

    // ---------- cluster gather: bsx/bsy + lamuda ----------
    cluster_sync_();
    {
        int i0 = rk * EN + tid;
        int i1 = i0 + NT;
        float bsx0 = 0.f, bsy0 = 0.f, bsx1 = 0.f, bsy1 = 0.f;
#pragma unroll
        for (int k = 0; k < KK; k++) {
            bsx0 += dsmem_ldf(&sbuf0[i0], 2 * k);
            bsy0 += dsmem_ldf(&sbuf0[i0], 2 * k + 1);
            bsx1 += dsmem_ldf(&sbuf0[i1], 2 * k);
            bsy1 += dsmem_ldf(&sbuf0[i1], 2 * k + 1);
        }
        d_out[OUT_BSX + giE0] = bsx0;
        d_out[OUT_BSY + giE0] = bsy0;
        d_out[OUT_LAM + giE0] = lamE0 + na * (u_buf[i0] + bsx0 + bsy0 - sE0);
        d_out[OUT_BSX + giE1] = bsx1;
        d_out[OUT_BSY + giE1] = bsy1;
        d_out[OUT_LAM + giE1] = lamE1 + na * (u_buf[i1] + bsx1 + bsy1 - sE1);
    }
    cluster_sync_();
}

// ---------------- launch ---------------------------------------------------
extern "C" void kernel_launch(void* const* d_in, const int* in_sizes, int n_in,
                              void* d_out_v, int out_size)
{
    const float* s      = (const float*)d_in[0];
    const float* eIF    = (const float*)d_in[1];
    const float* xm     = (const float*)d_in[2];
    const float* ym     = (const float*)d_in[3];
    const float* sum_x  = (const float*)d_in[4];
    const float* sum_y  = (const float*)d_in[5];
    const float* lamuda = (const float*)d_in[6];
    const float* initf  = (const float*)d_in[7];
    const int*   mmask  = (const int*)  d_in[8];
    const float* alpha  = (const float*)d_in[9];
    const float* beta   = (const float*)d_in[10];
    const float* var    = (const float*)d_in[11];
    const float* fs     = (const float*)d_in[12];
    const int*   iter   = (const int*)  d_in[13];
    const float* fe_w1  = (const float*)d_in[14];
    const float* fe_b1  = (const float*)d_in[15];
    const float* fe_w2  = (const float*)d_in[16];
    const float* fe_b2  = (const float*)d_in[17];
    const float* pr_w1  = (const float*)d_in[18];
    const float* pr_b1  = (const float*)d_in[19];
    const float* pr_w2  = (const float*)d_in[20];
    const float* pr_b2  = (const float*)d_in[21];
    const float* pr_w3  = (const float*)d_in[22];
    const float* pr_b3  = (const float*)d_in[23];
    const float* iw     = (const float*)d_in[24];
    float* d_out = (float*)d_out_v;

    fused_kernel<<<NGRID, NT>>>(s, eIF, xm, ym, sum_x, sum_y, lamuda, mmask,
                                initf, alpha, beta, var, fs, iter,
                                fe_w1, fe_b1, fe_w2, fe_b2,
                                pr_w1, pr_b1, pr_w2, pr_b2, pr_w3, pr_b3,
                                iw, d_out);
}